// round 1
// baseline (speedup 1.0000x reference)
#include <cuda_runtime.h>
#include <mma.h>
using namespace nvcuda;

#define NB 2
#define L 6400
#define S 6400
#define C 256
#define GRID_W 80
#define BORDER 2

static constexpr float SIM_SCALE = 1.0f / 25.6f;   // 1/(C*TEMPERATURE)
static constexpr float THRESH = 0.2f;
static constexpr long long NLS = (long long)NB * L * S;

// small per-launch stats scratch (sanctioned __device__ globals)
__device__ float g_rowsum[NB * L];
__device__ float g_colsum[NB * S];
__device__ float g_invrow[NB * L];
__device__ float g_invcol[NB * S];
__device__ float g_rowmax[NB * L];
__device__ int   g_colmax[NB * S];   // float bits; conf >= 0 so int order == float order

// ---------------------------------------------------------------------------
// 0) zero the atomically-accumulated stats (must run every launch: graph replay)
// ---------------------------------------------------------------------------
__global__ void init_stats_k() {
    int i = blockIdx.x * blockDim.x + threadIdx.x;
    if (i < NB * S) { g_colsum[i] = 0.0f; g_colmax[i] = 0; }
}

// ---------------------------------------------------------------------------
// 1) TF32 WMMA GEMM: E[n,l,s] = exp( dot(x0[n,l,:], x1[n,s,:]) / 25.6 )
//    CTA tile 128x128, BK=32, 8 warps (2x4), warp tile 64x32 (4x2 wmma frags)
// ---------------------------------------------------------------------------
#define BM 128
#define BN 128
#define BK 32
#define LDS_PAD 4

__global__ __launch_bounds__(256) void gemm_exp_k(
    const float* __restrict__ x0, const float* __restrict__ x1,
    float* __restrict__ E)
{
    __shared__ float As[BM][BK + LDS_PAD];
    __shared__ float Bs[BN][BK + LDS_PAD];

    const int n  = blockIdx.z;
    const int l0 = blockIdx.y * BM;
    const int s0 = blockIdx.x * BN;

    const float* A  = x0 + (size_t)n * L * C;
    const float* B  = x1 + (size_t)n * S * C;
    float*       Eo = E  + (size_t)n * L * S;

    const int t   = threadIdx.x;
    const int wid = t >> 5;
    const int wm  = wid >> 2;   // 0..1  -> 64 rows each
    const int wn  = wid & 3;    // 0..3  -> 32 cols each

    wmma::fragment<wmma::accumulator, 16, 16, 8, float> acc[4][2];
    #pragma unroll
    for (int i = 0; i < 4; i++)
        #pragma unroll
        for (int j = 0; j < 2; j++)
            wmma::fill_fragment(acc[i][j], 0.0f);

    for (int k0 = 0; k0 < C; k0 += BK) {
        // cooperative tile load: 128x32 floats each for A and B (float4)
        #pragma unroll
        for (int i = 0; i < 4; i++) {
            int idx = t + i * 256;          // 0..1023
            int r   = idx >> 3;             // row 0..127
            int c   = (idx & 7) << 2;       // col 0,4,..,28
            *(float4*)&As[r][c] = *(const float4*)(A + (size_t)(l0 + r) * C + k0 + c);
            *(float4*)&Bs[r][c] = *(const float4*)(B + (size_t)(s0 + r) * C + k0 + c);
        }
        __syncthreads();

        #pragma unroll
        for (int kk = 0; kk < BK; kk += 8) {
            wmma::fragment<wmma::matrix_a, 16, 16, 8, wmma::precision::tf32, wmma::row_major> af[4];
            wmma::fragment<wmma::matrix_b, 16, 16, 8, wmma::precision::tf32, wmma::col_major> bf[2];
            #pragma unroll
            for (int i = 0; i < 4; i++) {
                wmma::load_matrix_sync(af[i], &As[wm * 64 + i * 16][kk], BK + LDS_PAD);
                #pragma unroll
                for (int e = 0; e < af[i].num_elements; e++)
                    af[i].x[e] = wmma::__float_to_tf32(af[i].x[e]);
            }
            #pragma unroll
            for (int j = 0; j < 2; j++) {
                wmma::load_matrix_sync(bf[j], &Bs[wn * 32 + j * 16][kk], BK + LDS_PAD);
                #pragma unroll
                for (int e = 0; e < bf[j].num_elements; e++)
                    bf[j].x[e] = wmma::__float_to_tf32(bf[j].x[e]);
            }
            #pragma unroll
            for (int i = 0; i < 4; i++)
                #pragma unroll
                for (int j = 0; j < 2; j++)
                    wmma::mma_sync(acc[i][j], af[i], bf[j], acc[i][j]);
        }
        __syncthreads();
    }

    // epilogue: E = exp(sim). |sim| <= ~4 so no max-subtraction needed.
    #pragma unroll
    for (int i = 0; i < 4; i++) {
        #pragma unroll
        for (int j = 0; j < 2; j++) {
            #pragma unroll
            for (int e = 0; e < acc[i][j].num_elements; e++)
                acc[i][j].x[e] = __expf(acc[i][j].x[e] * SIM_SCALE);
            wmma::store_matrix_sync(
                &Eo[(size_t)(l0 + wm * 64 + i * 16) * S + (s0 + wn * 32 + j * 16)],
                acc[i][j], S, wmma::mem_row_major);
        }
    }
}

// ---------------------------------------------------------------------------
// block reduce helpers
// ---------------------------------------------------------------------------
__device__ __forceinline__ float block_reduce_sum(float v) {
    __shared__ float sh[8];
    #pragma unroll
    for (int o = 16; o; o >>= 1) v += __shfl_xor_sync(0xFFFFFFFFu, v, o);
    if ((threadIdx.x & 31) == 0) sh[threadIdx.x >> 5] = v;
    __syncthreads();
    if (threadIdx.x < 32) {
        v = (threadIdx.x < 8) ? sh[threadIdx.x] : 0.0f;
        #pragma unroll
        for (int o = 4; o; o >>= 1) v += __shfl_xor_sync(0xFFFFFFFFu, v, o);
    }
    return v;  // valid in thread 0
}

__device__ __forceinline__ float block_reduce_max(float v) {
    __shared__ float sh[8];
    #pragma unroll
    for (int o = 16; o; o >>= 1) v = fmaxf(v, __shfl_xor_sync(0xFFFFFFFFu, v, o));
    if ((threadIdx.x & 31) == 0) sh[threadIdx.x >> 5] = v;
    __syncthreads();
    if (threadIdx.x < 32) {
        v = (threadIdx.x < 8) ? sh[threadIdx.x] : 0.0f;
        #pragma unroll
        for (int o = 4; o; o >>= 1) v = fmaxf(v, __shfl_xor_sync(0xFFFFFFFFu, v, o));
    }
    return v;
}

// ---------------------------------------------------------------------------
// 2) per-row sums of E (deterministic, one block per row)
// ---------------------------------------------------------------------------
__global__ __launch_bounds__(256) void rowsum_k(const float* __restrict__ E) {
    const int n = blockIdx.y, l = blockIdx.x;
    const float* row = E + ((size_t)n * L + l) * S;
    float s = 0.0f;
    for (int i = threadIdx.x; i < S; i += 256) s += row[i];
    float r = block_reduce_sum(s);
    if (threadIdx.x == 0) g_rowsum[n * L + l] = r;
}

// ---------------------------------------------------------------------------
// 3) per-column sums of E (chunked over rows for parallelism, atomicAdd)
// ---------------------------------------------------------------------------
#define COL_CHUNKS 32
#define ROWS_PER_CHUNK (L / COL_CHUNKS)   // 200

__global__ __launch_bounds__(256) void colsum_k(const float* __restrict__ E) {
    const int n = blockIdx.z;
    const int s = blockIdx.x * 256 + threadIdx.x;
    const int chunk = blockIdx.y;
    const float* base = E + (size_t)n * L * S + (size_t)chunk * ROWS_PER_CHUNK * S + s;
    float a = 0.0f;
    #pragma unroll 4
    for (int l = 0; l < ROWS_PER_CHUNK; l++) a += base[(size_t)l * S];
    atomicAdd(&g_colsum[n * S + s], a);
}

// ---------------------------------------------------------------------------
// 4) reciprocals
// ---------------------------------------------------------------------------
__global__ void inv_k() {
    int i = blockIdx.x * blockDim.x + threadIdx.x;
    if (i < NB * L) {
        g_invrow[i] = 1.0f / g_rowsum[i];
        g_invcol[i] = 1.0f / g_colsum[i];
    }
}

// ---------------------------------------------------------------------------
// 5) conf = E^2 * invrow * invcol  (write conf + exact per-row max)
// ---------------------------------------------------------------------------
__global__ __launch_bounds__(256) void conf_k(const float* __restrict__ E,
                                              float* __restrict__ conf) {
    const int n = blockIdx.y, l = blockIdx.x;
    const size_t off = ((size_t)n * L + l) * S;
    const float ir = g_invrow[n * L + l];
    float m = 0.0f;
    for (int s = threadIdx.x; s < S; s += 256) {
        float e = E[off + s];
        float c = e * e * ir * g_invcol[n * S + s];
        conf[off + s] = c;
        m = fmaxf(m, c);
    }
    float r = block_reduce_max(m);
    if (threadIdx.x == 0) g_rowmax[n * L + l] = r;
}

// ---------------------------------------------------------------------------
// 6) per-column max of conf (chunked, atomicMax on bits; conf > 0)
// ---------------------------------------------------------------------------
__global__ __launch_bounds__(256) void colmax_k(const float* __restrict__ conf) {
    const int n = blockIdx.z;
    const int s = blockIdx.x * 256 + threadIdx.x;
    const int chunk = blockIdx.y;
    const float* base = conf + (size_t)n * L * S + (size_t)chunk * ROWS_PER_CHUNK * S + s;
    float m = 0.0f;
    #pragma unroll 4
    for (int l = 0; l < ROWS_PER_CHUNK; l++) m = fmaxf(m, base[(size_t)l * S]);
    atomicMax(&g_colmax[n * S + s], __float_as_int(m));
}

// ---------------------------------------------------------------------------
// 7) mask + scores
// ---------------------------------------------------------------------------
__global__ __launch_bounds__(256) void final_k(const float* __restrict__ conf,
                                               float* __restrict__ maskp,
                                               float* __restrict__ scoresp) {
    const int n = blockIdx.y, l = blockIdx.x;
    const size_t off = ((size_t)n * L + l) * S;
    const float rmax = g_rowmax[n * L + l];
    const int h0 = l / GRID_W, w0 = l % GRID_W;
    const bool v0 = (h0 >= BORDER) && (h0 < GRID_W - BORDER) &&
                    (w0 >= BORDER) && (w0 < GRID_W - BORDER);
    for (int s = threadIdx.x; s < S; s += 256) {
        float c = conf[off + s];
        int h1 = s / GRID_W, w1 = s % GRID_W;
        bool v1 = (h1 >= BORDER) && (h1 < GRID_W - BORDER) &&
                  (w1 >= BORDER) && (w1 < GRID_W - BORDER);
        bool m = v0 && v1 && (c > THRESH) &&
                 (c == rmax) && (c == __int_as_float(g_colmax[n * S + s]));
        maskp[off + s]   = m ? 1.0f : 0.0f;
        scoresp[off + s] = m ? c    : 0.0f;
    }
}

// ---------------------------------------------------------------------------
extern "C" void kernel_launch(void* const* d_in, const int* in_sizes, int n_in,
                              void* d_out, int out_size) {
    const float* x0 = (const float*)d_in[0];
    const float* x1 = (const float*)d_in[1];

    float* conf    = (float*)d_out;          // [NB, L, S]
    float* maskp   = conf + NLS;             // [NB, L, S] (bool as float)
    float* scoresp = conf + 2 * NLS;         // [NB, L, S]
    float* E       = scoresp;                // scratch: exp(sim), overwritten by scores last

    init_stats_k<<<(NB * S + 255) / 256, 256>>>();
    gemm_exp_k<<<dim3(S / BN, L / BM, NB), 256>>>(x0, x1, E);
    rowsum_k<<<dim3(L, NB), 256>>>(E);
    colsum_k<<<dim3(S / 256, COL_CHUNKS, NB), 256>>>(E);
    inv_k<<<(NB * L + 255) / 256, 256>>>();
    conf_k<<<dim3(L, NB), 256>>>(E, conf);
    colmax_k<<<dim3(S / 256, COL_CHUNKS, NB), 256>>>(conf);
    final_k<<<dim3(L, NB), 256>>>(conf, maskp, scoresp);
}

// round 3
// speedup vs baseline: 2.4089x; 2.4089x over previous
#include <cuda_runtime.h>
#include <cuda_fp16.h>
#include <mma.h>
#include <cstdint>
using namespace nvcuda;

#define NB 2
#define L 6400
#define S 6400
#define C 256
#define GRID_W 80
#define BORDER 2

static constexpr float SIM_SCALE = 1.0f / 25.6f;   // 1/(C*TEMPERATURE)
static constexpr float THRESH = 0.2f;
static constexpr long long NLS = (long long)NB * L * S;

#define BM 128
#define BN 128
#define BK 32
#define NKT (C / BK)            // 8
#define SSTR 48                 // smem half stride (96B, 16B-aligned rows)
#define STAGE_STRIDE 132        // floats
#define A_BUF_BYTES (2 * BM * SSTR * 2)        // 24576
#define SMEM_BYTES  (BM * STAGE_STRIDE * 4)    // 67584 (stage overlays A/B bufs)

// ---- scratch (static __device__ globals: allowed) ----
__device__ __align__(16) __half g_h0[NB * L * C];
__device__ __align__(16) __half g_h1[NB * S * C];
__device__ float g_rowsum[NB * L];
__device__ float g_colsum[NB * S];
__device__ float g_invrow[NB * L];
__device__ float g_invcol[NB * S];
__device__ float g_rowmax[NB * L];
__device__ int   g_rowarg[NB * L];
__device__ int   g_colmax[NB * S];   // float bits; conf > 0 so int order == float order

// ---------------------------------------------------------------------------
__device__ __forceinline__ uint32_t smem_u32(const void* p) {
    uint32_t a;
    asm("{ .reg .u64 t; cvta.to.shared.u64 t, %1; cvt.u32.u64 %0, t; }" : "=r"(a) : "l"(p));
    return a;
}
__device__ __forceinline__ void cp_async16(uint32_t saddr, const void* gaddr) {
    asm volatile("cp.async.cg.shared.global [%0], [%1], 16;" :: "r"(saddr), "l"(gaddr));
}
#define CP_COMMIT() asm volatile("cp.async.commit_group;" ::: "memory")
#define CP_WAIT(n)  asm volatile("cp.async.wait_group %0;" :: "n"(n) : "memory")

// ---------------------------------------------------------------------------
// 0) float -> half conversion of both inputs
// ---------------------------------------------------------------------------
#define CVT_CHUNKS (NB * L * C / 4)   // 1,638,400 float4-chunks per tensor
__global__ __launch_bounds__(256) void cvt_k(const float4* __restrict__ x0,
                                             const float4* __restrict__ x1) {
    int i = blockIdx.x * blockDim.x + threadIdx.x;
    if (i < CVT_CHUNKS) {
        float4 v = x0[i];
        __half2* o = (__half2*)g_h0;
        o[2 * i]     = __floats2half2_rn(v.x, v.y);
        o[2 * i + 1] = __floats2half2_rn(v.z, v.w);
    } else if (i < 2 * CVT_CHUNKS) {
        int j = i - CVT_CHUNKS;
        float4 v = x1[j];
        __half2* o = (__half2*)g_h1;
        o[2 * j]     = __floats2half2_rn(v.x, v.y);
        o[2 * j + 1] = __floats2half2_rn(v.z, v.w);
    }
}

// ---------------------------------------------------------------------------
// 1) zero atomically-accumulated stats (must run on every graph replay)
// ---------------------------------------------------------------------------
__global__ void init_stats_k() {
    int i = blockIdx.x * blockDim.x + threadIdx.x;
    if (i < NB * S) { g_colsum[i] = 0.0f; g_colmax[i] = 0; g_rowsum[i] = 0.0f; }
}

// ---------------------------------------------------------------------------
// 2) FP16 WMMA GEMM, cp.async double-buffered, fused exp + row/col sums
//    E[n,l,s] = exp( dot(x0[n,l,:], x1[n,s,:]) / 25.6 )
// ---------------------------------------------------------------------------
__global__ __launch_bounds__(256) void gemm_exp_k(float* __restrict__ E) {
    extern __shared__ char smem[];
    __half* As = (__half*)smem;                        // [2][BM][SSTR]
    __half* Bs = (__half*)(smem + A_BUF_BYTES);        // [2][BN][SSTR]
    float*  stage = (float*)smem;                      // overlays after mainloop
    const uint32_t sAs = smem_u32(As), sBs = smem_u32(Bs);

    const int t = threadIdx.x;
    const int wid = t >> 5;
    const int wm = wid >> 2;       // 0..1 -> 64 rows
    const int wn = wid & 3;        // 0..3 -> 32 cols
    const int n = blockIdx.z;
    const int l0 = blockIdx.y * BM, s0 = blockIdx.x * BN;

    const __half* A = g_h0 + (size_t)n * L * C;
    const __half* B = g_h1 + (size_t)n * S * C;
    float* Eo = E + (size_t)n * L * S;

    wmma::fragment<wmma::accumulator, 16, 16, 16, float> acc[4][2];
    #pragma unroll
    for (int i = 0; i < 4; i++)
        #pragma unroll
        for (int j = 0; j < 2; j++)
            wmma::fill_fragment(acc[i][j], 0.0f);

    // tile loader: 128x32 halves per matrix, 512 16B-chunks, 256 threads x2
    auto load_tile = [&](int kt, int buf) {
        const int k0 = kt * BK;
        const uint32_t boff = buf * BM * SSTR * 2;
        #pragma unroll
        for (int i = 0; i < 2; i++) {
            int c = t + i * 256;               // 0..511
            int r = c >> 2, u = c & 3;         // row, 8-half group
            uint32_t so = (uint32_t)(r * SSTR + u * 8) * 2 + boff;
            cp_async16(sAs + so, A + (size_t)(l0 + r) * C + k0 + u * 8);
            cp_async16(sBs + so, B + (size_t)(s0 + r) * C + k0 + u * 8);
        }
        CP_COMMIT();
    };

    load_tile(0, 0);

    for (int kt = 0; kt < NKT; kt++) {
        if (kt + 1 < NKT) { load_tile(kt + 1, (kt + 1) & 1); CP_WAIT(1); }
        else              { CP_WAIT(0); }
        __syncthreads();

        const __half* Ab = As + (kt & 1) * BM * SSTR;
        const __half* Bb = Bs + (kt & 1) * BN * SSTR;
        #pragma unroll
        for (int ks = 0; ks < BK; ks += 16) {
            wmma::fragment<wmma::matrix_a, 16, 16, 16, __half, wmma::row_major> af[4];
            wmma::fragment<wmma::matrix_b, 16, 16, 16, __half, wmma::col_major> bf[2];
            #pragma unroll
            for (int i = 0; i < 4; i++)
                wmma::load_matrix_sync(af[i], Ab + (wm * 64 + i * 16) * SSTR + ks, SSTR);
            #pragma unroll
            for (int j = 0; j < 2; j++)
                wmma::load_matrix_sync(bf[j], Bb + (wn * 32 + j * 16) * SSTR + ks, SSTR);
            #pragma unroll
            for (int i = 0; i < 4; i++)
                #pragma unroll
                for (int j = 0; j < 2; j++)
                    wmma::mma_sync(acc[i][j], af[i], bf[j], acc[i][j]);
        }
        __syncthreads();   // before buffer reuse / stage overlay
    }

    // ---- epilogue: exp, stage to smem, row/col partial sums, coalesced store
    #pragma unroll
    for (int i = 0; i < 4; i++) {
        #pragma unroll
        for (int j = 0; j < 2; j++) {
            #pragma unroll
            for (int e = 0; e < acc[i][j].num_elements; e++)
                acc[i][j].x[e] = __expf(acc[i][j].x[e] * SIM_SCALE);
            wmma::store_matrix_sync(
                &stage[(size_t)(wm * 64 + i * 16) * STAGE_STRIDE + wn * 32 + j * 16],
                acc[i][j], STAGE_STRIDE, wmma::mem_row_major);
        }
    }
    __syncthreads();

    // row partial sums: thread t -> row t&127, col half t>>7
    {
        const int r = t & 127, h = t >> 7;
        float s = 0.0f;
        #pragma unroll 16
        for (int c = 0; c < 64; c++) s += stage[r * STAGE_STRIDE + h * 64 + c];
        atomicAdd(&g_rowsum[n * L + l0 + r], s);
    }
    // col partial sums: thread t -> col t&127, row half t>>7
    {
        const int c = t & 127, h = t >> 7;
        float s = 0.0f;
        #pragma unroll 16
        for (int r = 0; r < 64; r++) s += stage[(h * 64 + r) * STAGE_STRIDE + c];
        atomicAdd(&g_colsum[n * S + s0 + c], s);
    }
    // coalesced E store
    #pragma unroll
    for (int it = 0; it < 16; it++) {
        int idx = t + it * 256;            // 0..4095
        int r = idx >> 5, q = idx & 31;
        *(float4*)&Eo[(size_t)(l0 + r) * S + s0 + q * 4] =
            *(float4*)&stage[r * STAGE_STRIDE + q * 4];
    }
}

// ---------------------------------------------------------------------------
// 3) reciprocals
// ---------------------------------------------------------------------------
__global__ void inv_k() {
    int i = blockIdx.x * blockDim.x + threadIdx.x;
    if (i < NB * L) {
        g_invrow[i] = 1.0f / g_rowsum[i];
        g_invcol[i] = 1.0f / g_colsum[i];
    }
}

// ---------------------------------------------------------------------------
// 4) conf = E^2*invrow*invcol; rowmax+argmax, colmax (32-row stripes)
// ---------------------------------------------------------------------------
#define CROWS 32
__global__ __launch_bounds__(256) void conf_k(const float* __restrict__ E,
                                              float* __restrict__ conf) {
    const int n = blockIdx.y;
    const int l0 = blockIdx.x * CROWS;
    const int t = threadIdx.x;
    __shared__ float s_val[8];
    __shared__ int   s_arg[8];

    float ic[25], cm[25];
    #pragma unroll
    for (int k = 0; k < 25; k++) { ic[k] = g_invcol[n * S + t + k * 256]; cm[k] = 0.0f; }

    for (int r = 0; r < CROWS; r++) {
        const int l = l0 + r;
        const size_t off = ((size_t)n * L + l) * S;
        const float ir = g_invrow[n * L + l];
        float rmax = 0.0f; int rarg = t;
        #pragma unroll
        for (int k = 0; k < 25; k++) {
            int s = t + k * 256;
            float e = E[off + s];
            float c = e * e * ir * ic[k];
            conf[off + s] = c;
            cm[k] = fmaxf(cm[k], c);
            if (c > rmax) { rmax = c; rarg = s; }
        }
        #pragma unroll
        for (int o = 16; o; o >>= 1) {
            float ov = __shfl_xor_sync(0xFFFFFFFFu, rmax, o);
            int   oa = __shfl_xor_sync(0xFFFFFFFFu, rarg, o);
            if (ov > rmax) { rmax = ov; rarg = oa; }
        }
        if ((t & 31) == 0) { s_val[t >> 5] = rmax; s_arg[t >> 5] = rarg; }
        __syncthreads();
        if (t == 0) {
            #pragma unroll
            for (int w = 1; w < 8; w++)
                if (s_val[w] > rmax) { rmax = s_val[w]; rarg = s_arg[w]; }
            g_rowmax[n * L + l] = rmax;
            g_rowarg[n * L + l] = rarg;
        }
        __syncthreads();
    }
    #pragma unroll
    for (int k = 0; k < 25; k++)
        atomicMax(&g_colmax[n * S + t + k * 256], __float_as_int(cm[k]));
}

// ---------------------------------------------------------------------------
// 5) sparse final: only mutual-argmax candidates can be masked
// ---------------------------------------------------------------------------
__device__ __forceinline__ bool border_ok(int i) {
    int h = i / GRID_W, w = i % GRID_W;
    return (h >= BORDER) && (h < GRID_W - BORDER) && (w >= BORDER) && (w < GRID_W - BORDER);
}
__global__ void final_sparse_k(float* __restrict__ maskp, float* __restrict__ scoresp) {
    int i = blockIdx.x * blockDim.x + threadIdx.x;
    if (i >= NB * L) return;
    int n = i / L, l = i % L;
    float rmax = g_rowmax[i];
    int s = g_rowarg[i];
    if (rmax > THRESH &&
        __float_as_int(rmax) == g_colmax[n * S + s] &&
        border_ok(l) && border_ok(s)) {
        size_t off = ((size_t)n * L + l) * S + s;
        maskp[off] = 1.0f;
        scoresp[off] = rmax;
    }
}

// ---------------------------------------------------------------------------
extern "C" void kernel_launch(void* const* d_in, const int* in_sizes, int n_in,
                              void* d_out, int out_size) {
    const float* x0 = (const float*)d_in[0];
    const float* x1 = (const float*)d_in[1];

    float* conf    = (float*)d_out;          // [NB, L, S]
    float* maskp   = conf + NLS;             // [NB, L, S]
    float* scoresp = conf + 2 * NLS;         // [NB, L, S]
    float* E       = scoresp;                // scratch (consumed before memset)

    cudaFuncSetAttribute(gemm_exp_k, cudaFuncAttributeMaxDynamicSharedMemorySize, SMEM_BYTES);

    cvt_k<<<(2 * CVT_CHUNKS + 255) / 256, 256>>>((const float4*)x0, (const float4*)x1);
    init_stats_k<<<(NB * S + 255) / 256, 256>>>();
    gemm_exp_k<<<dim3(S / BN, L / BM, NB), 256, SMEM_BYTES>>>(E);
    inv_k<<<(NB * L + 255) / 256, 256>>>();
    conf_k<<<dim3(L / CROWS, NB), 256>>>(E, conf);
    cudaMemsetAsync(maskp, 0, (size_t)2 * NLS * sizeof(float));
    final_sparse_k<<<(NB * L + 255) / 256, 256>>>(maskp, scoresp);
}